// round 17
// baseline (speedup 1.0000x reference)
#include <cuda_runtime.h>
#include <cuda_fp16.h>
#include <math.h>
#include <stdint.h>

// ---------------------------------------------------------------------------
// SupPatchNCELoss — GB300 (sm_103a), round 16: int8 IMMA Gram (m16n8k32)
//
// loss = mean_i [ log S1_i - (S2_i - cnt_i) * (1/T) / cnt_i ]
//   S1_i = sum_{j!=i} exp((cos_ij - 1)/T)
//   S2_i = sum_{j!=i, lab_j==lab_i} cos_ij
//   cnt_i = 2*hist[lab_i] - 1
//
// R16 vs R11/R15: Gram in int8 (per-row symmetric quantization, exact s32
// accumulation, cos = s_i*s_j*acc). IMMA m16n8k32 doubles MAC/instruction on
// the legacy tensor pipe (the R15-identified wall). Whole-K single-stage smem
// tiles (32 KB each) remove all per-k-stage barriers. Fragment byte layout is
// identical to the verified fp16 LDSM path. Epilogue/partials unchanged.
// ---------------------------------------------------------------------------

#define NPATCH 4096
#define MROWS  8192
#define CDIM   256
#define HSEG   128
#define INV_T  (1.0f / 0.07f)

#define NT 64
#define NPAIRS (NT * (NT + 1) / 2)   // 2080

#define ROWB 272                     // smem row stride bytes (17 chunks: conflict-free)
#define TILE_SMEM (128 * ROWB)       // 34816 B per tile
#define DYN_BYTES (2 * TILE_SMEM)    // 69632 B

__device__ int    g_qnt[MROWS * CDIM / 4];   // packed int8 features (2 MB)
__device__ float  g_scale[MROWS];            // per-row quant scale
__device__ int    g_lab[NPATCH];
__device__ int    g_hist[8];
__device__ float  g_S1p[NT][MROWS];
__device__ float  g_S2p[NT][MROWS];
__device__ float  g_part[128];

// ---------------------------------------------------------------------------
__device__ __forceinline__ unsigned sptr(const void* p) {
    return (unsigned)__cvta_generic_to_shared(p);
}
__device__ __forceinline__ void mma_s8(int c[4], const unsigned a[4],
                                       const unsigned b[2]) {
    asm volatile(
        "mma.sync.aligned.m16n8k32.row.col.s32.s8.s8.s32 "
        "{%0,%1,%2,%3}, {%4,%5,%6,%7}, {%8,%9}, {%0,%1,%2,%3};\n"
        : "+r"(c[0]), "+r"(c[1]), "+r"(c[2]), "+r"(c[3])
        : "r"(a[0]), "r"(a[1]), "r"(a[2]), "r"(a[3]), "r"(b[0]), "r"(b[1]));
}
#define LDSM_X4(r0, r1, r2, r3, a) \
    asm volatile("ldmatrix.sync.aligned.m8n8.x4.shared.b16 {%0,%1,%2,%3}, [%4];" \
        : "=r"(r0), "=r"(r1), "=r"(r2), "=r"(r3) : "r"(a))
__device__ __forceinline__ void cpa16(unsigned smem, const void* gp) {
    asm volatile("cp.async.cg.shared.global [%0], [%1], 16;\n"
                 :: "r"(smem), "l"(gp));
}
#define CP_COMMIT() asm volatile("cp.async.commit_group;\n" ::: "memory")
#define CP_WAIT0()  asm volatile("cp.async.wait_group 0;\n" ::: "memory")

// ---------------------------------------------------------------------------
// 1) labels + histogram (single block)
// ---------------------------------------------------------------------------
__global__ void labels_kernel(const int* __restrict__ seg,
                              const int* __restrict__ coords,
                              const int* __restrict__ crw,
                              const int* __restrict__ crh,
                              const int* __restrict__ crd) {
    __shared__ int sh_hist[8];
    int t = threadIdx.x;
    if (t < 8) sh_hist[t] = 0;
    __syncthreads();
    int cw = *crw, ch = *crh, cd = *crd;
    for (int p = t; p < NPATCH; p += blockDim.x) {
        int cx = coords[p * 3 + 0];
        int cy = coords[p * 3 + 1];
        int cz = coords[p * 3 + 2];
        int ix = (cx * HSEG) / cw;
        int iy = (cy * HSEG) / ch;
        int iz = (cz * HSEG) / cd;
        int l = seg[(ix * HSEG + iy) * HSEG + iz];
        g_lab[p] = l;
        atomicAdd(&sh_hist[l & 7], 1);
    }
    __syncthreads();
    if (t < 8) g_hist[t] = sh_hist[t];
}

// ---------------------------------------------------------------------------
// 2) row-normalize + int8 quantize: one warp per row
//    q_k = round(127 * f_k / max|f|)  (normalization cancels)
//    scale s = max|f| * inv_norm / 127, so that s * q = f_hat
// ---------------------------------------------------------------------------
__global__ void normalize_kernel(const float* __restrict__ f) {
    int warp = (blockIdx.x * blockDim.x + threadIdx.x) >> 5;
    int lane = threadIdx.x & 31;
    if (warp >= MROWS) return;
    const float4* src = (const float4*)(f + (size_t)warp * CDIM);
    float4 v0 = src[lane];
    float4 v1 = src[lane + 32];
    float ss = v0.x * v0.x + v0.y * v0.y + v0.z * v0.z + v0.w * v0.w
             + v1.x * v1.x + v1.y * v1.y + v1.z * v1.z + v1.w * v1.w;
    float ma = fmaxf(fmaxf(fmaxf(fabsf(v0.x), fabsf(v0.y)),
                           fmaxf(fabsf(v0.z), fabsf(v0.w))),
                     fmaxf(fmaxf(fabsf(v1.x), fabsf(v1.y)),
                           fmaxf(fabsf(v1.z), fabsf(v1.w))));
    #pragma unroll
    for (int o = 16; o > 0; o >>= 1) {
        ss += __shfl_xor_sync(0xffffffffu, ss, o);
        ma = fmaxf(ma, __shfl_xor_sync(0xffffffffu, ma, o));
    }
    ma = fmaxf(ma, 1e-20f);
    float inv = rsqrtf(fmaxf(ss, 1e-24f));
    float qs = 127.0f / ma;
    int q0 = __float2int_rn(v0.x * qs), q1 = __float2int_rn(v0.y * qs);
    int q2 = __float2int_rn(v0.z * qs), q3 = __float2int_rn(v0.w * qs);
    int q4 = __float2int_rn(v1.x * qs), q5 = __float2int_rn(v1.y * qs);
    int q6 = __float2int_rn(v1.z * qs), q7 = __float2int_rn(v1.w * qs);
    int p0 = (q0 & 255) | ((q1 & 255) << 8) | ((q2 & 255) << 16) | ((q3 & 255) << 24);
    int p1 = (q4 & 255) | ((q5 & 255) << 8) | ((q6 & 255) << 16) | ((q7 & 255) << 24);
    g_qnt[warp * 64 + lane]      = p0;   // cols lane*4 .. lane*4+3
    g_qnt[warp * 64 + 32 + lane] = p1;   // cols 128+lane*4 ..
    if (lane == 0)
        g_scale[warp] = ma * inv * (1.0f / 127.0f);
}

// ---------------------------------------------------------------------------
// 3) symmetric Gram + fused epilogue, int8 IMMA + LDSM, whole-K tiles.
//    2080 blocks, 256 threads = 8 warps (wy in {0,1}, wx in {0..3}),
//    warp tile 64x32, block tile 128x128, K = 256 in 8 IMMA k32-steps.
// ---------------------------------------------------------------------------
__global__ __launch_bounds__(256, 2) void gram_kernel() {
    extern __shared__ char dynb[];
    unsigned Abase = sptr(dynb);
    unsigned Bbase = Abase + TILE_SMEM;

    __shared__ int   labR[128], labC[128];
    __shared__ float scR[128], scC[128];
    __shared__ float sR1[4][128], sR2[4][128];
    __shared__ float sC1[2][128], sC2[2][128];

    // linear block -> (I, J) with I <= J
    int b = blockIdx.x;
    int I = 0;
    while (b >= NT - I) { b -= NT - I; I++; }
    int J = I + b;
    int rowBase = I * 128, colBase = J * 128;

    int tid  = threadIdx.x;
    int lane = tid & 31, w = tid >> 5;
    int wy = w >> 2, wx = w & 3;
    int g = lane >> 2, t4 = lane & 3;

    if (tid < 128) {
        labR[tid] = g_lab[(rowBase + tid) & (NPATCH - 1)];
        scR[tid]  = g_scale[rowBase + tid];
    } else {
        labC[tid - 128] = g_lab[(colBase + tid - 128) & (NPATCH - 1)];
        scC[tid - 128]  = g_scale[colBase + tid - 128];
    }

    // whole-K tile loads: 128 rows x 256 B = 2048 chunks of 16B per tile
    const char* gq = (const char*)g_qnt;
    #pragma unroll
    for (int i = 0; i < 8; i++) {
        int idx = tid + i * 256;          // 0..2047
        int row = idx >> 4;               // 0..127
        int ch  = (idx & 15) * 16;        // byte offset in row
        cpa16(Abase + row * ROWB + ch, gq + (size_t)(rowBase + row) * CDIM + ch);
        cpa16(Bbase + row * ROWB + ch, gq + (size_t)(colBase + row) * CDIM + ch);
    }
    CP_COMMIT();

    // LDSM per-lane address components (byte-identical to verified fp16 map)
    int m_   = lane >> 3;
    int rowp = (m_ & 1) * 8 + (lane & 7);
    int colpB = (m_ >> 1) * 16;           // byte offset within k32 chunk

    int acc[4][4][4];
    #pragma unroll
    for (int mi = 0; mi < 4; mi++)
        #pragma unroll
        for (int ni = 0; ni < 4; ni++)
            #pragma unroll
            for (int q = 0; q < 4; q++) acc[mi][ni][q] = 0;

    CP_WAIT0();
    __syncthreads();

    #pragma unroll
    for (int ks = 0; ks < 8; ks++) {
        int kb = ks * 32;                 // k bytes this step
        unsigned af[4][4], bf[4][2];
        #pragma unroll
        for (int mi = 0; mi < 4; mi++) {
            unsigned a = Abase
                + (unsigned)((wy * 64 + mi * 16 + rowp) * ROWB + kb + colpB);
            LDSM_X4(af[mi][0], af[mi][1], af[mi][2], af[mi][3], a);
        }
        #pragma unroll
        for (int nb = 0; nb < 2; nb++) {
            unsigned a = Bbase
                + (unsigned)((wx * 32 + nb * 16 + rowp) * ROWB + kb + colpB);
            LDSM_X4(bf[2 * nb][0], bf[2 * nb + 1][0],
                    bf[2 * nb][1], bf[2 * nb + 1][1], a);
        }
        #pragma unroll
        for (int mi = 0; mi < 4; mi++)
            #pragma unroll
            for (int ni = 0; ni < 4; ni++)
                mma_s8(acc[mi][ni], af[mi], bf[ni]);
    }

    // ---- fused epilogue: cos = sI*sJ*acc; exp-sum + label-masked cos-sum ----
    float cs1[4][2], cs2[4][2];
    #pragma unroll
    for (int ni = 0; ni < 4; ni++) {
        cs1[ni][0] = 0.f; cs1[ni][1] = 0.f;
        cs2[ni][0] = 0.f; cs2[ni][1] = 0.f;
    }
    bool diag = (I == J);

    #pragma unroll
    for (int mi = 0; mi < 4; mi++) {
        float rs1[2] = {0.f, 0.f}, rs2[2] = {0.f, 0.f};
        int lr0 = wy * 64 + mi * 16 + g;
        int lr1 = lr0 + 8;
        int labr0 = labR[lr0], labr1 = labR[lr1];
        float sr0 = scR[lr0], sr1 = scR[lr1];
        #pragma unroll
        for (int ni = 0; ni < 4; ni++) {
            int lc0 = wx * 32 + ni * 8 + 2 * t4;
            int lc1 = lc0 + 1;
            int labc0 = labC[lc0], labc1 = labC[lc1];
            float sc0 = scC[lc0], sc1 = scC[lc1];
            #pragma unroll
            for (int q = 0; q < 4; q++) {
                int lr = (q & 2) ? lr1 : lr0;
                int lc = (q & 1) ? lc1 : lc0;
                int lbr = (q & 2) ? labr1 : labr0;
                int lbc = (q & 1) ? labc1 : labc0;
                float sr = (q & 2) ? sr1 : sr0;
                float sc = (q & 1) ? sc1 : sc0;
                float v = (float)acc[mi][ni][q] * (sr * sc);
                bool self = diag && (lr == lc);
                float e = __expf((v - 1.0f) * INV_T);
                if (!self) {
                    rs1[(q >> 1)] += e;
                    cs1[ni][(q & 1)] += e;
                    if (lbr == lbc) {
                        rs2[(q >> 1)] += v;
                        cs2[ni][(q & 1)] += v;
                    }
                }
            }
        }
        #pragma unroll
        for (int h = 0; h < 2; h++) {
            float v1 = rs1[h], v2 = rs2[h];
            v1 += __shfl_xor_sync(0xffffffffu, v1, 1);
            v1 += __shfl_xor_sync(0xffffffffu, v1, 2);
            v2 += __shfl_xor_sync(0xffffffffu, v2, 1);
            v2 += __shfl_xor_sync(0xffffffffu, v2, 2);
            if (t4 == 0) {
                int lr = wy * 64 + mi * 16 + h * 8 + g;
                sR1[wx][lr] = v1;
                sR2[wx][lr] = v2;
            }
        }
    }

    #pragma unroll
    for (int ni = 0; ni < 4; ni++) {
        #pragma unroll
        for (int h = 0; h < 2; h++) {
            float v1 = cs1[ni][h], v2 = cs2[ni][h];
            v1 += __shfl_xor_sync(0xffffffffu, v1, 4);
            v1 += __shfl_xor_sync(0xffffffffu, v1, 8);
            v1 += __shfl_xor_sync(0xffffffffu, v1, 16);
            v2 += __shfl_xor_sync(0xffffffffu, v2, 4);
            v2 += __shfl_xor_sync(0xffffffffu, v2, 8);
            v2 += __shfl_xor_sync(0xffffffffu, v2, 16);
            if (g == 0) {
                int lc = wx * 32 + ni * 8 + 2 * t4 + h;
                sC1[wy][lc] = v1;
                sC2[wy][lc] = v2;
            }
        }
    }
    __syncthreads();

    // deterministic partial writes: slot = other tile index
    if (tid < 128) {
        int r = tid;
        g_S1p[J][rowBase + r] = sR1[0][r] + sR1[1][r] + sR1[2][r] + sR1[3][r];
        g_S2p[J][rowBase + r] = sR2[0][r] + sR2[1][r] + sR2[2][r] + sR2[3][r];
    } else if (I < J) {
        int c = tid - 128;
        g_S1p[I][colBase + c] = sC1[0][c] + sC1[1][c];
        g_S2p[I][colBase + c] = sC2[0][c] + sC2[1][c];
    }
}

// ---------------------------------------------------------------------------
// 4) final reduction: 128 blocks x 256 threads; 64 rows/block, 4-way split
// ---------------------------------------------------------------------------
__global__ void final1_kernel() {
    __shared__ float p1[4][64], p2[4][64];
    __shared__ float sh[64];
    int r6   = threadIdx.x & 63;
    int part = threadIdx.x >> 6;
    int row  = blockIdx.x * 64 + r6;
    float S1 = 0.0f, S2 = 0.0f;
    #pragma unroll
    for (int s = part * 16; s < part * 16 + 16; s++) {
        S1 += g_S1p[s][row];
        S2 += g_S2p[s][row];
    }
    p1[part][r6] = S1;
    p2[part][r6] = S2;
    __syncthreads();
    if (part == 0) {
        float fS1 = p1[0][r6] + p1[1][r6] + p1[2][r6] + p1[3][r6];
        float fS2 = p2[0][r6] + p2[1][r6] + p2[2][r6] + p2[3][r6];
        int lb = g_lab[row & (NPATCH - 1)] & 7;
        float cnt = (float)(2 * g_hist[lb] - 1);
        sh[r6] = logf(fS1) - (fS2 - cnt) * (INV_T / cnt);
    }
    __syncthreads();
    if (threadIdx.x < 32) {
        float v = sh[threadIdx.x] + sh[threadIdx.x + 32];
        #pragma unroll
        for (int o = 16; o > 0; o >>= 1)
            v += __shfl_xor_sync(0xffffffffu, v, o);
        if (threadIdx.x == 0) g_part[blockIdx.x] = v;
    }
}

__global__ void final2_kernel(float* __restrict__ out) {
    __shared__ float sh[128];
    sh[threadIdx.x] = g_part[threadIdx.x];
    __syncthreads();
    for (int o = 64; o > 0; o >>= 1) {
        if (threadIdx.x < o) sh[threadIdx.x] += sh[threadIdx.x + o];
        __syncthreads();
    }
    if (threadIdx.x == 0) out[0] = sh[0] / (float)MROWS;
}

// ---------------------------------------------------------------------------
extern "C" void kernel_launch(void* const* d_in, const int* in_sizes, int n_in,
                              void* d_out, int out_size) {
    const float* features = (const float*)d_in[0];
    const int*   seg      = (const int*)d_in[1];
    const int*   coords   = (const int*)d_in[2];
    const int*   crw      = (const int*)d_in[3];
    const int*   crh      = (const int*)d_in[4];
    const int*   crd      = (const int*)d_in[5];
    float* out = (float*)d_out;

    static bool attr_set = false;
    if (!attr_set) {
        cudaFuncSetAttribute(gram_kernel,
                             cudaFuncAttributeMaxDynamicSharedMemorySize,
                             DYN_BYTES);
        attr_set = true;
    }

    labels_kernel<<<1, 256>>>(seg, coords, crw, crh, crd);
    normalize_kernel<<<MROWS / 8, 256>>>(features);
    gram_kernel<<<NPAIRS, 256, DYN_BYTES>>>();
    final1_kernel<<<128, 256>>>();
    final2_kernel<<<1, 128>>>(out);
}